// round 7
// baseline (speedup 1.0000x reference)
#include <cuda_runtime.h>
#include <cuda_fp16.h>

// Shapes (fixed by the problem): M=1024, K=4096, N=4096, group size 128.
#define K_DIM 4096
#define N_DIM 4096
#define M_DIM 1024

// Scratch (no cudaMalloc allowed): dequantized W [K,N] fp16 (32 MB) and
// x converted to fp16 [M,K] (8 MB). Harness passes fp16 tensors as float32.
__device__ __half g_W[(size_t)K_DIM * N_DIM];
__device__ __half g_X[(size_t)M_DIM * K_DIM];

// ---------------------------------------------------------------------------
// Kernel 0: convert x float32 -> fp16 (lossless: data was originally fp16).
// ---------------------------------------------------------------------------
__global__ void convert_x_kernel(const float* __restrict__ x, size_t n) {
    size_t i = ((size_t)blockIdx.x * blockDim.x + threadIdx.x) * 8;
    if (i >= n) return;
    float4 a = *(const float4*)&x[i];
    float4 b = *(const float4*)&x[i + 4];
    __half2 h0 = __floats2half2_rn(a.x, a.y);
    __half2 h1 = __floats2half2_rn(a.z, a.w);
    __half2 h2 = __floats2half2_rn(b.x, b.y);
    __half2 h3 = __floats2half2_rn(b.z, b.w);
    *(__half2*)&g_X[i]     = h0;
    *(__half2*)&g_X[i + 2] = h1;
    *(__half2*)&g_X[i + 4] = h2;
    *(__half2*)&g_X[i + 6] = h3;
}

// ---------------------------------------------------------------------------
// Kernel 1: GPTQ 4-bit dequant -> g_W[K][N] fp16
//   qweight int32 [K/8, N]  (8 x 4-bit packed along K)
//   qzeros  int32 [G, N/8]  (8 x 4-bit packed along N)
//   scales  float [G, N]  (fp16 upcast by harness)
//   w[k][n] = (q - (z + 1)) * scale[g][n]
// ---------------------------------------------------------------------------
__global__ void dequant_kernel(const int* __restrict__ qw,
                               const float* __restrict__ scales,
                               const int* __restrict__ qz,
                               const int* __restrict__ gidx,
                               int K, int N) {
    int kp  = blockIdx.y;          // 0 .. K/8-1
    int n0  = blockIdx.x * 256;
    int tid = threadIdx.x;
    int n   = n0 + tid;

    __shared__ __align__(16) __half tile[8][256];

    int g = gidx[kp * 8];          // all 8 k in this word share a group (GS=128)
    unsigned q  = (unsigned)qw[(size_t)kp * N + n];
    unsigned zw = (unsigned)qz[(size_t)g * (N >> 3) + (n >> 3)];
    float z1 = (float)((zw >> ((n & 7) * 4)) & 15u) + 1.0f;
    float s  = scales[(size_t)g * N + n];

#pragma unroll
    for (int j = 0; j < 8; j++) {
        float w = ((float)((q >> (j * 4)) & 15u) - z1) * s;
        tile[j][tid] = __float2half(w);
    }
    __syncthreads();

    int k0 = kp * 8;
#pragma unroll
    for (int i = 0; i < 4; i++) {
        int idx = i * 256 + tid;     // 0..1023 half2 slots (8 rows x 128)
        int r   = idx >> 7;          // 0..7
        int c   = (idx & 127) * 2;   // half column
        __half2 v = *(const __half2*)&tile[r][c];
        *(__half2*)&g_W[(size_t)(k0 + r) * N + n0 + c] = v;
    }
}

// ---------------------------------------------------------------------------
// Kernel 2: fp16 GEMM  out[M][N] = g_X[M][K] @ g_W[K][N] + bias, fp32 accum.
// 128x128 CTA tile, BK=32, 8 warps (4m x 2n), mma.sync m16n8k16,
// cp.async double-buffered pipeline, swizzled SMEM for ldmatrix.
// ---------------------------------------------------------------------------
#define BM 128
#define BN 128
#define BK 32

__device__ __forceinline__ void cp16(unsigned dst, const __half* src) {
    size_t gsrc = __cvta_generic_to_global((const void*)src);
    asm volatile("cp.async.cg.shared.global [%0], [%1], 16;\n" :: "r"(dst), "l"(gsrc));
}
__device__ __forceinline__ void ldm_x4(unsigned* r, unsigned addr) {
    asm volatile("ldmatrix.sync.aligned.m8n8.x4.shared.b16 {%0,%1,%2,%3}, [%4];"
                 : "=r"(r[0]), "=r"(r[1]), "=r"(r[2]), "=r"(r[3]) : "r"(addr));
}
__device__ __forceinline__ void ldm_x4_t(unsigned* r, unsigned addr) {
    asm volatile("ldmatrix.sync.aligned.m8n8.x4.trans.shared.b16 {%0,%1,%2,%3}, [%4];"
                 : "=r"(r[0]), "=r"(r[1]), "=r"(r[2]), "=r"(r[3]) : "r"(addr));
}
__device__ __forceinline__ void mma16816(float* d, const unsigned* a, unsigned b0, unsigned b1) {
    asm volatile("mma.sync.aligned.m16n8k16.row.col.f32.f16.f16.f32 "
                 "{%0,%1,%2,%3}, {%4,%5,%6,%7}, {%8,%9}, {%0,%1,%2,%3};"
                 : "+f"(d[0]), "+f"(d[1]), "+f"(d[2]), "+f"(d[3])
                 : "r"(a[0]), "r"(a[1]), "r"(a[2]), "r"(a[3]), "r"(b0), "r"(b1));
}

__global__ __launch_bounds__(256, 2)
void gemm_kernel(const float* __restrict__ bias,
                 float* __restrict__ out,
                 int M, int N, int K) {
    __shared__ __align__(16) __half As[2][BM * BK];   // 8 KB per stage
    __shared__ __align__(16) __half Bs[2][BK * BN];   // 8 KB per stage

    const int tid  = threadIdx.x;
    const int lane = tid & 31;
    const int warp = tid >> 5;
    const int wm   = (warp & 3) * 32;   // warp m offset within CTA tile
    const int wn   = (warp >> 2) * 64;  // warp n offset within CTA tile
    const int mb   = blockIdx.y * BM;
    const int nb   = blockIdx.x * BN;

    const unsigned sA = (unsigned)__cvta_generic_to_shared(As);
    const unsigned sB = (unsigned)__cvta_generic_to_shared(Bs);

    float acc[2][8][4];
#pragma unroll
    for (int i = 0; i < 2; i++)
#pragma unroll
        for (int j = 0; j < 8; j++)
#pragma unroll
            for (int c = 0; c < 4; c++) acc[i][j][c] = 0.0f;

    const int NKC = K / BK;   // 128 k-chunks

    // -------- async load of one k-chunk into stage buffers --------
    // A tile: 128 rows x 32 halfs = 4 chunks/row of 16B. slot = c ^ (m&3)
    // B tile:  32 rows x 128 halfs = 16 chunks/row.       slot = c ^ (k&7)
    auto issue = [&](int stage, int kc) {
        int k0 = kc * BK;
#pragma unroll
        for (int t = 0; t < 2; t++) {
            int idx = t * 256 + tid;          // 0..511
            int m = idx >> 2, c = idx & 3;
            const __half* src = g_X + (size_t)(mb + m) * K + k0 + c * 8;
            unsigned dst = sA + stage * (BM * BK * 2) + (m * 4 + (c ^ (m & 3))) * 16;
            cp16(dst, src);
        }
#pragma unroll
        for (int t = 0; t < 2; t++) {
            int idx = t * 256 + tid;          // 0..511
            int k = idx >> 4, c = idx & 15;
            const __half* src = g_W + (size_t)(k0 + k) * N + nb + c * 8;
            unsigned dst = sB + stage * (BK * BN * 2) + (k * 16 + (c ^ (k & 7))) * 16;
            cp16(dst, src);
        }
    };

    issue(0, 0);
    asm volatile("cp.async.commit_group;\n");

    for (int kc = 0; kc < NKC; ++kc) {
        int stage = kc & 1;
        if (kc + 1 < NKC) {
            issue(stage ^ 1, kc + 1);
            asm volatile("cp.async.commit_group;\n");
            asm volatile("cp.async.wait_group 1;\n");
        } else {
            asm volatile("cp.async.wait_group 0;\n");
        }
        __syncthreads();

        const unsigned baseA = sA + stage * (BM * BK * 2);
        const unsigned baseB = sB + stage * (BK * BN * 2);

#pragma unroll
        for (int kk = 0; kk < 2; kk++) {       // two k16 steps per chunk
            unsigned a[2][4];
#pragma unroll
            for (int mi = 0; mi < 2; mi++) {
                int row = wm + mi * 16 + (lane & 15);
                int c   = kk * 2 + (lane >> 4);
                unsigned addr = baseA + (row * 4 + (c ^ (row & 3))) * 16;
                ldm_x4(a[mi], addr);
            }
            unsigned b[4][4];
#pragma unroll
            for (int nt = 0; nt < 4; nt++) {
                int row = kk * 16 + (lane & 15);
                int c   = ((wn + nt * 16) >> 3) + (lane >> 4);
                unsigned addr = baseB + (row * 16 + (c ^ (row & 7))) * 16;
                ldm_x4_t(b[nt], addr);
            }
#pragma unroll
            for (int mi = 0; mi < 2; mi++)
#pragma unroll
                for (int nj = 0; nj < 8; nj++) {
                    int nt = nj >> 1, h = nj & 1;
                    mma16816(acc[mi][nj], a[mi], b[nt][h * 2], b[nt][h * 2 + 1]);
                }
        }
        __syncthreads();
    }

    // -------- epilogue: + bias (float), fp32 out --------
    const int gq = lane >> 2, tq = lane & 3;
#pragma unroll
    for (int mi = 0; mi < 2; mi++) {
        int row0 = mb + wm + mi * 16 + gq;
#pragma unroll
        for (int nj = 0; nj < 8; nj++) {
            int col = nb + wn + nj * 8 + tq * 2;
            float b0 = bias[col];
            float b1 = bias[col + 1];
            float2 v0 = make_float2(acc[mi][nj][0] + b0, acc[mi][nj][1] + b1);
            float2 v1 = make_float2(acc[mi][nj][2] + b0, acc[mi][nj][3] + b1);
            *(float2*)&out[(size_t)row0 * N + col]       = v0;
            *(float2*)&out[(size_t)(row0 + 8) * N + col] = v1;
        }
    }
}

// ---------------------------------------------------------------------------
// Launch: inputs in metadata order: x, qweight, scales, qzeros, g_idx, bias
// fp16 tensors (x, scales, bias) arrive upcast to float32.
// ---------------------------------------------------------------------------
extern "C" void kernel_launch(void* const* d_in, const int* in_sizes, int n_in,
                              void* d_out, int out_size) {
    const float* x       = (const float*)d_in[0];
    const int*   qweight = (const int*)d_in[1];
    const float* scales  = (const float*)d_in[2];
    const int*   qzeros  = (const int*)d_in[3];
    const int*   g_idx   = (const int*)d_in[4];
    const float* bias    = (const float*)d_in[5];
    float*       out     = (float*)d_out;

    const int K = in_sizes[4];          // g_idx length
    const int N = in_sizes[5];          // bias length
    const int M = in_sizes[0] / K;      // x is [M, K]

    // 0) convert x f32 -> f16
    size_t nx = (size_t)M * K;
    convert_x_kernel<<<(unsigned)((nx / 8 + 255) / 256), 256>>>(x, nx);

    // 1) dequant int4 -> fp16 W [K, N]
    dim3 gd(N / 256, K / 8);
    dequant_kernel<<<gd, 256>>>(qweight, scales, qzeros, g_idx, K, N);

    // 2) GEMM + bias
    dim3 gg(N / BN, M / BM);
    gemm_kernel<<<gg, 256>>>(bias, out, M, N, K);
}